// round 10
// baseline (speedup 1.0000x reference)
#include <cuda_runtime.h>
#include <math.h>

#define HID  300
#define G3   900
#define BMOL 2048
#define MAXL 48
#define NTOT (BMOL * MAXL)   // 98304
#define NKT  38              // ceil(300/8)

// ---------------- static scratch (no runtime allocation allowed) ----------------
__device__ int   g_counts[BMOL];
__device__ int   g_offsets[BMOL];
__device__ float g_xp[(size_t)2 * NTOT * G3];   // xp (+b_ih), per direction
__device__ float g_hp[2 * BMOL * G3];           // hp (+b_hh), per direction, per step
__device__ float g_h[2][2][BMOL * HID];         // [dir][pingpong][B*H]

// ---------------- setup kernels ----------------
__global__ void k_init() {
    int i = blockIdx.x * blockDim.x + threadIdx.x;
    if (i < BMOL) g_counts[i] = 0;
}

__global__ void k_count(const int* __restrict__ batch) {
    int i = blockIdx.x * blockDim.x + threadIdx.x;
    if (i < NTOT) atomicAdd(&g_counts[batch[i]], 1);
}

// inclusive scan of counts -> exclusive offsets (2048 elems, one block of 1024 threads)
__global__ void k_scan() {
    __shared__ int s[BMOL];
    int t = threadIdx.x;
    s[t]        = g_counts[t];
    s[t + 1024] = g_counts[t + 1024];
    __syncthreads();
    for (int off = 1; off < BMOL; off <<= 1) {
        int i0 = t, i1 = t + 1024;
        int v0 = (i0 >= off) ? s[i0 - off] : 0;
        int v1 = (i1 >= off) ? s[i1 - off] : 0;
        __syncthreads();
        s[i0] += v0;
        s[i1] += v1;
        __syncthreads();
    }
    g_offsets[t]        = s[t]        - g_counts[t];
    g_offsets[t + 1024] = s[t + 1024] - g_counts[t + 1024];
}

// h0[b] = segment max of raw x over the molecule's rows; same h0 for both dirs
__global__ void k_h0(const float* __restrict__ x) {
    int b = blockIdx.x;
    int off = g_offsets[b], cnt = g_counts[b];
    for (int j = threadIdx.x; j < HID; j += blockDim.x) {
        float m = -3.402823e38f;
        for (int r = 0; r < cnt; r++)
            m = fmaxf(m, x[(size_t)(off + r) * HID + j]);
        g_h[0][0][b * HID + j] = m;
        g_h[1][0][b * HID + j] = m;
    }
}

// ---------------- GEMM: C[M,G3] = A[M,300] * W[G3,300]^T + bo ----------------
// XP=true : A(i,k) = relu(x[i,k] + bias[k]), C = g_xp[dir]   (M = NTOT)
// XP=false: A = g_h[dir][s&1],               C = g_hp[dir]   (M = BMOL)
template <bool XP>
__global__ __launch_bounds__(256) void k_gemm(
    const float* __restrict__ xA, const float* __restrict__ bias,
    const float* __restrict__ Wf, const float* __restrict__ Wb,
    const float* __restrict__ bf, const float* __restrict__ bb,
    int s)
{
    int dir = blockIdx.z;
    const float* W  = dir ? Wb : Wf;
    const float* bo = dir ? bb : bf;
    const float* A;
    float* C;
    if (XP) { A = xA;              C = g_xp + (size_t)dir * NTOT * G3; }
    else    { A = g_h[dir][s & 1]; C = g_hp + (size_t)dir * BMOL * G3; }

    __shared__ float As[2][8][128];
    __shared__ float Bs[2][8][128];

    int tid = threadIdx.x;
    int lr  = tid >> 1;         // 0..127 : row within tile (A) / weight row (B)
    int lk4 = tid & 1;          // which half of the 8-wide k slab
    int ag  = blockIdx.x * 128 + lr;   // global A row (always valid: M % 128 == 0)
    int bg  = blockIdx.y * 128 + lr;   // global W row
    bool bok = bg < G3;

    float acc[8][8];
#pragma unroll
    for (int i = 0; i < 8; i++)
#pragma unroll
        for (int j = 0; j < 8; j++) acc[i][j] = 0.f;

    auto load = [&](int kt, int st) {
        int k = kt * 8 + lk4 * 4;
        float4 va = make_float4(0.f, 0.f, 0.f, 0.f);
        float4 vb = make_float4(0.f, 0.f, 0.f, 0.f);
        if (k < HID) {  // k is a multiple of 4 and HID%4==0 -> full float4 in range
            va = *(const float4*)(A + (size_t)ag * HID + k);
            if (XP) {
                va.x = fmaxf(va.x + bias[k + 0], 0.f);
                va.y = fmaxf(va.y + bias[k + 1], 0.f);
                va.z = fmaxf(va.z + bias[k + 2], 0.f);
                va.w = fmaxf(va.w + bias[k + 3], 0.f);
            }
            if (bok) vb = *(const float4*)(W + (size_t)bg * HID + k);
        }
        As[st][lk4 * 4 + 0][lr] = va.x;
        As[st][lk4 * 4 + 1][lr] = va.y;
        As[st][lk4 * 4 + 2][lr] = va.z;
        As[st][lk4 * 4 + 3][lr] = va.w;
        Bs[st][lk4 * 4 + 0][lr] = vb.x;
        Bs[st][lk4 * 4 + 1][lr] = vb.y;
        Bs[st][lk4 * 4 + 2][lr] = vb.z;
        Bs[st][lk4 * 4 + 3][lr] = vb.w;
    };

    load(0, 0);
    __syncthreads();

    int ty = tid >> 4, tx = tid & 15;
    for (int kt = 0; kt < NKT; kt++) {
        if (kt + 1 < NKT) load(kt + 1, (kt + 1) & 1);
        int st = kt & 1;
#pragma unroll
        for (int kk = 0; kk < 8; kk++) {
            float a[8], b[8];
            *(float4*)(a)     = *(const float4*)(&As[st][kk][ty * 8]);
            *(float4*)(a + 4) = *(const float4*)(&As[st][kk][ty * 8 + 4]);
            *(float4*)(b)     = *(const float4*)(&Bs[st][kk][tx * 8]);
            *(float4*)(b + 4) = *(const float4*)(&Bs[st][kk][tx * 8 + 4]);
#pragma unroll
            for (int i = 0; i < 8; i++)
#pragma unroll
                for (int j = 0; j < 8; j++) acc[i][j] += a[i] * b[j];
        }
        __syncthreads();
    }

    int rbase = blockIdx.x * 128 + ty * 8;
    int cbase = blockIdx.y * 128 + tx * 8;
#pragma unroll
    for (int i = 0; i < 8; i++) {
        size_t ro = (size_t)(rbase + i) * G3;
#pragma unroll
        for (int j = 0; j < 8; j++) {
            int cg = cbase + j;
            if (cg < G3) C[ro + cg] = acc[i][j] + bo[cg];
        }
    }
}

// ---------------- per-step gate fusion ----------------
__global__ void k_gates(const float* __restrict__ bihf,
                        const float* __restrict__ bihb,
                        float* __restrict__ out, int s)
{
    int idx = blockIdx.x * blockDim.x + threadIdx.x;
    if (idx >= 2 * BMOL * HID) return;
    int dir = idx / (BMOL * HID);
    int rem = idx - dir * (BMOL * HID);
    int b = rem / HID;
    int j = rem - b * HID;

    int cnt = g_counts[b], off = g_offsets[b];
    int t = dir ? (MAXL - 1 - s) : s;
    bool valid = t < cnt;

    const float* bih = dir ? bihb : bihf;
    const float* xp  = g_xp + (size_t)dir * NTOT * G3;

    float xr, xz, xn;
    if (valid) {
        size_t ro = (size_t)(off + t) * G3 + j;
        xr = xp[ro]; xz = xp[ro + HID]; xn = xp[ro + 2 * HID];
    } else {  // padded row: message==0 -> xp == b_ih
        xr = bih[j]; xz = bih[j + HID]; xn = bih[j + 2 * HID];
    }
    const float* hp = g_hp + (size_t)dir * BMOL * G3 + (size_t)b * G3 + j;
    float hr = hp[0], hz = hp[HID], hn = hp[2 * HID];
    float hold = g_h[dir][s & 1][b * HID + j];

    float r = 1.f / (1.f + expf(-(xr + hr)));
    float z = 1.f / (1.f + expf(-(xz + hz)));
    float n = tanhf(xn + r * hn);
    float hnew = (1.f - z) * n + z * hold;

    g_h[dir][(s + 1) & 1][b * HID + j] = hnew;
    if (valid)
        out[(size_t)(off + t) * (2 * HID) + (size_t)dir * HID + j] = hnew;
}

// ---------------- launch ----------------
extern "C" void kernel_launch(void* const* d_in, const int* in_sizes, int n_in,
                              void* d_out, int out_size)
{
    const float* x     = (const float*)d_in[0];
    const int*   batch = (const int*)  d_in[1];
    // scalars num_moles / max_len may or may not appear in d_in; resolve bias
    // index from sizes (bias has 300 elements).
    int ib = 2;
    while (ib < n_in && in_sizes[ib] != HID) ib++;
    const float* bias  = (const float*)d_in[ib + 0];
    const float* wihf  = (const float*)d_in[ib + 1];
    const float* whhf  = (const float*)d_in[ib + 2];
    const float* bihf  = (const float*)d_in[ib + 3];
    const float* bhhf  = (const float*)d_in[ib + 4];
    const float* wihb  = (const float*)d_in[ib + 5];
    const float* whhb  = (const float*)d_in[ib + 6];
    const float* bihb  = (const float*)d_in[ib + 7];
    const float* bhhb  = (const float*)d_in[ib + 8];
    float* out = (float*)d_out;

    k_init <<<(BMOL + 255) / 256, 256>>>();
    k_count<<<(NTOT + 255) / 256, 256>>>(batch);
    k_scan <<<1, 1024>>>();
    k_h0   <<<BMOL, 64>>>(x);

    // NOTE argument order: (xA, bias, Wf, Wb, bf, bb, s)
    dim3 gx(NTOT / 128, (G3 + 127) / 128, 2);
    k_gemm<true><<<gx, 256>>>(x, bias, wihf, wihb, bihf, bihb, 0);

    dim3 gh(BMOL / 128, (G3 + 127) / 128, 2);
    for (int s = 0; s < MAXL; s++) {
        k_gemm<false><<<gh, 256>>>(nullptr, nullptr, whhf, whhb, bhhf, bhhb, s);
        k_gates<<<(2 * BMOL * HID + 255) / 256, 256>>>(bihf, bihb, out, s);
    }
}

// round 13
// speedup vs baseline: 1.8827x; 1.8827x over previous
#include <cuda_runtime.h>
#include <cuda_bf16.h>
#include <stdint.h>
#include <math.h>

#define HID 300
#define G3  900
#define KP  320              // K padded to 10 x 32
#define WROWS 1024           // padded W rows (tile-7 OOB safety)
#define BMOL 2048
#define MAXL 48
#define NTOT (BMOL*MAXL)     // 98304

// ---------------- static scratch ----------------
__device__ int   g_counts[BMOL];
__device__ int   g_offsets[BMOL];
__device__ __align__(256) float g_xp[(size_t)2*NTOT*G3];
__device__ __align__(256) float g_hp[2*BMOL*G3];
__device__ __align__(256) float g_h[2][2][BMOL*HID];
__device__ __align__(256) __nv_bfloat16 g_msgH[(size_t)NTOT*KP];
__device__ __align__(256) __nv_bfloat16 g_msgL[(size_t)NTOT*KP];
__device__ __align__(256) __nv_bfloat16 g_wH[4][WROWS*KP];  // 0 wih_f, 1 wih_b, 2 whh_f, 3 whh_b
__device__ __align__(256) __nv_bfloat16 g_wL[4][WROWS*KP];
__device__ __align__(256) __nv_bfloat16 g_hH[2][BMOL*KP];
__device__ __align__(256) __nv_bfloat16 g_hL[2][BMOL*KP];

// ---------------- PTX helpers (baseline ISA only) ----------------
__device__ __forceinline__ uint32_t s2u(const void* p){
    uint32_t a; asm("{ .reg .u64 t; cvta.to.shared.u64 t, %1; cvt.u32.u64 %0, t; }":"=r"(a):"l"(p)); return a; }
__device__ __forceinline__ void ld16(uint32_t dst, const void* src){
    asm volatile("cp.async.cg.shared.global [%0], [%1], 16;" :: "r"(dst), "l"(src) : "memory"); }
#define CP_COMMIT() asm volatile("cp.async.commit_group;" ::: "memory")
#define CP_WAIT1()  asm volatile("cp.async.wait_group 1;" ::: "memory")
#define CP_WAIT0()  asm volatile("cp.async.wait_group 0;" ::: "memory")
__device__ __forceinline__ void ldm4(uint32_t* r, uint32_t addr){
    asm volatile("ldmatrix.sync.aligned.m8n8.x4.shared.b16 {%0,%1,%2,%3}, [%4];"
        : "=r"(r[0]),"=r"(r[1]),"=r"(r[2]),"=r"(r[3]) : "r"(addr)); }
__device__ __forceinline__ void mma16816(float* c, const uint32_t* a, uint32_t b0, uint32_t b1){
    asm volatile("mma.sync.aligned.m16n8k16.row.col.f32.bf16.bf16.f32 "
        "{%0,%1,%2,%3}, {%4,%5,%6,%7}, {%8,%9}, {%0,%1,%2,%3};"
        : "+f"(c[0]),"+f"(c[1]),"+f"(c[2]),"+f"(c[3])
        : "r"(a[0]),"r"(a[1]),"r"(a[2]),"r"(a[3]), "r"(b0),"r"(b1)); }

// ---------------- setup kernels ----------------
__global__ void k_init() {
    int i = blockIdx.x * blockDim.x + threadIdx.x;
    if (i < BMOL) g_counts[i] = 0;
}
__global__ void k_count(const int* __restrict__ batch) {
    int i = blockIdx.x * blockDim.x + threadIdx.x;
    if (i < NTOT) atomicAdd(&g_counts[batch[i]], 1);
}
__global__ void k_scan() {
    __shared__ int s[BMOL];
    int t = threadIdx.x;
    s[t] = g_counts[t]; s[t+1024] = g_counts[t+1024];
    __syncthreads();
    for (int off = 1; off < BMOL; off <<= 1) {
        int v0 = (t >= off) ? s[t-off] : 0;
        int v1 = (t+1024 >= off) ? s[t+1024-off] : 0;
        __syncthreads();
        s[t] += v0; s[t+1024] += v1;
        __syncthreads();
    }
    g_offsets[t] = s[t] - g_counts[t];
    g_offsets[t+1024] = s[t+1024] - g_counts[t+1024];
}
__global__ void k_h0(const float* __restrict__ x) {
    int b = blockIdx.x;
    int off = g_offsets[b], cnt = g_counts[b];
    for (int j = threadIdx.x; j < KP; j += blockDim.x) {
        if (j < HID) {
            float m = -3.402823e38f;
            int r = 0;
            for (; r + 3 < cnt; r += 4) {
                float a = x[(size_t)(off+r  )*HID + j];
                float c = x[(size_t)(off+r+1)*HID + j];
                float d = x[(size_t)(off+r+2)*HID + j];
                float e = x[(size_t)(off+r+3)*HID + j];
                m = fmaxf(m, fmaxf(fmaxf(a,c), fmaxf(d,e)));
            }
            for (; r < cnt; r++) m = fmaxf(m, x[(size_t)(off+r)*HID + j]);
            g_h[0][0][b*HID+j] = m; g_h[1][0][b*HID+j] = m;
            __nv_bfloat16 hi = __float2bfloat16(m);
            __nv_bfloat16 lo = __float2bfloat16(m - __bfloat162float(hi));
            g_hH[0][b*KP+j] = hi; g_hH[1][b*KP+j] = hi;
            g_hL[0][b*KP+j] = lo; g_hL[1][b*KP+j] = lo;
        } else {
            __nv_bfloat16 z = __float2bfloat16(0.f);
            g_hH[0][b*KP+j] = z; g_hH[1][b*KP+j] = z;
            g_hL[0][b*KP+j] = z; g_hL[1][b*KP+j] = z;
        }
    }
}
__global__ void k_msgsplit(const float* __restrict__ x, const float* __restrict__ bias) {
    int i = blockIdx.x * blockDim.x + threadIdx.x;
    if (i >= NTOT * KP) return;
    int row = i / KP, k = i - row * KP;
    float v = 0.f;
    if (k < HID) v = fmaxf(x[(size_t)row*HID + k] + bias[k], 0.f);
    __nv_bfloat16 hi = __float2bfloat16(v);
    __nv_bfloat16 lo = __float2bfloat16(v - __bfloat162float(hi));
    g_msgH[i] = hi; g_msgL[i] = lo;
}
__global__ void k_wsplit(const float* __restrict__ w0, const float* __restrict__ w1,
                         const float* __restrict__ w2, const float* __restrict__ w3) {
    int i = blockIdx.x * blockDim.x + threadIdx.x;
    if (i >= 4 * WROWS * KP) return;
    int m = i / (WROWS*KP);
    int rem = i - m * (WROWS*KP);
    int row = rem / KP, k = rem - row * KP;
    const float* src = (m==0)?w0:(m==1)?w1:(m==2)?w2:w3;
    float v = (row < G3 && k < HID) ? src[row*HID + k] : 0.f;
    __nv_bfloat16 hi = __float2bfloat16(v);
    __nv_bfloat16 lo = __float2bfloat16(v - __bfloat162float(hi));
    g_wH[m][rem] = hi; g_wL[m][rem] = lo;
}

// ---------------- mma.sync split-bf16 GEMM ----------------
// C[M,900] = A[M,300] @ W[900,300]^T + bo, fp32 via Ah*Wh + Ah*Wl + Al*Wh.
// mode 0: A = msg, W = wih[dir], C = g_xp[dir]  (M = NTOT, mtiles = 768)
// mode 1: A = h,   W = whh[dir], C = g_hp[dir]  (M = BMOL, mtiles = 16)
// grid (mtiles, 8, 2), block 256.
// Smem rows padded to 40 halves (80B) -> ldmatrix phases conflict-free.
__global__ __launch_bounds__(256) void k_gemm_mma(int mode,
                                                  const float* __restrict__ bo_f,
                                                  const float* __restrict__ bo_b)
{
    __shared__ __align__(16) __nv_bfloat16 sA[2][128*40];
    __shared__ __align__(16) __nv_bfloat16 sW[2][128*40];

    int tid = threadIdx.x, lane = tid & 31, wid = tid >> 5;
    int wm = wid >> 2, wn = wid & 3;     // warp tile: 64(M) x 32(N)
    int dir = blockIdx.z, ntile = blockIdx.y, mtile = blockIdx.x;

    const __nv_bfloat16 *AH, *AL, *WH, *WL;
    float* C;
    const float* bo = dir ? bo_b : bo_f;
    if (mode == 0) { AH=g_msgH;    AL=g_msgL;    WH=g_wH[dir];   WL=g_wL[dir];
                     C = g_xp + (size_t)dir*NTOT*G3; }
    else           { AH=g_hH[dir]; AL=g_hL[dir]; WH=g_wH[2+dir]; WL=g_wL[2+dir];
                     C = g_hp + (size_t)dir*BMOL*G3; }

    const size_t arow0 = (size_t)mtile * 128;
    const size_t nrow0 = (size_t)ntile * 128;
    const int lrow = tid >> 1;           // 0..127
    const int lc0  = (tid & 1) * 2;      // chunk 0..3 (16B each)

    uint32_t aB[2] = { s2u(sA[0]), s2u(sA[1]) };
    uint32_t wB[2] = { s2u(sW[0]), s2u(sW[1]) };
    uint32_t aDst0 = (uint32_t)(lrow*80 + lc0*16);

    auto load_slab = [&](int s, int buf){
        int p = s / 10, c = s - p*10, kb = c*32;
        const __nv_bfloat16* As = (p < 2) ? AH : AL;
        const __nv_bfloat16* Ws = (p == 1) ? WL : WH;
        const __nv_bfloat16* ga = As + (arow0 + lrow)*KP + kb + lc0*8;
        const __nv_bfloat16* gw = Ws + (nrow0 + lrow)*KP + kb + lc0*8;
        uint32_t da = aB[buf] + aDst0, dw = wB[buf] + aDst0;
        ld16(da,      ga);
        ld16(da + 16, ga + 8);
        ld16(dw,      gw);
        ld16(dw + 16, gw + 8);
        CP_COMMIT();
    };

    float acc[4][4][4];
#pragma unroll
    for (int i = 0; i < 4; i++)
#pragma unroll
        for (int j = 0; j < 4; j++)
#pragma unroll
            for (int k = 0; k < 4; k++) acc[i][j][k] = 0.f;

    // per-warp ldmatrix base offsets (within a buffer)
    uint32_t aLd = (uint32_t)((wm*64 + (lane & 15))*80 + (lane >> 4)*16);
    uint32_t wLd = (uint32_t)((wn*32 + ((lane >> 4) & 1)*8 + (lane & 7))*80 + ((lane >> 3) & 1)*16);

    load_slab(0, 0);
    for (int s = 0; s < 30; s++) {
        if (s < 29) { load_slab(s + 1, (s + 1) & 1); CP_WAIT1(); }
        else        { CP_WAIT0(); }
        __syncthreads();
        int buf = s & 1;
#pragma unroll
        for (int ks = 0; ks < 2; ks++) {
            uint32_t a[4][4], b[2][4];
#pragma unroll
            for (int mi = 0; mi < 4; mi++)
                ldm4(a[mi], aB[buf] + aLd + (uint32_t)(mi*16*80 + ks*32));
#pragma unroll
            for (int j = 0; j < 2; j++)
                ldm4(b[j], wB[buf] + wLd + (uint32_t)(j*16*80 + ks*32));
#pragma unroll
            for (int mi = 0; mi < 4; mi++)
#pragma unroll
                for (int ni = 0; ni < 4; ni++)
                    mma16816(acc[mi][ni], a[mi], b[ni>>1][(ni&1)*2], b[ni>>1][(ni&1)*2+1]);
        }
        __syncthreads();
    }

    // epilogue: bias add + store (cols >= 900 masked)
#pragma unroll
    for (int mi = 0; mi < 4; mi++) {
        int row0 = mtile*128 + wm*64 + mi*16 + (lane >> 2);
        size_t r0 = (size_t)row0 * G3, r8 = (size_t)(row0 + 8) * G3;
#pragma unroll
        for (int ni = 0; ni < 4; ni++) {
            int col = ntile*128 + wn*32 + ni*8 + (lane & 3)*2;
            if (col < G3) {
                float b0 = __ldg(bo + col), b1 = __ldg(bo + col + 1);
                C[r0 + col]     = acc[mi][ni][0] + b0;
                C[r0 + col + 1] = acc[mi][ni][1] + b1;
                C[r8 + col]     = acc[mi][ni][2] + b0;
                C[r8 + col + 1] = acc[mi][ni][3] + b1;
            }
        }
    }
}

// ---------------- per-step gate fusion ----------------
__global__ void k_gates(const float* __restrict__ bihf,
                        const float* __restrict__ bihb,
                        float* __restrict__ out, int s)
{
    int idx = blockIdx.x * blockDim.x + threadIdx.x;
    if (idx >= 2 * BMOL * HID) return;
    int dir = idx / (BMOL * HID);
    int rem = idx - dir * (BMOL * HID);
    int b = rem / HID;
    int j = rem - b * HID;

    int cnt = g_counts[b], off = g_offsets[b];
    int t = dir ? (MAXL - 1 - s) : s;
    bool valid = t < cnt;

    const float* bih = dir ? bihb : bihf;
    const float* xp  = g_xp + (size_t)dir * NTOT * G3;

    float xr, xz, xn;
    if (valid) {
        size_t ro = (size_t)(off + t) * G3 + j;
        xr = xp[ro]; xz = xp[ro + HID]; xn = xp[ro + 2*HID];
    } else {
        xr = bih[j]; xz = bih[j + HID]; xn = bih[j + 2*HID];
    }
    const float* hp = g_hp + (size_t)dir * BMOL * G3 + (size_t)b * G3 + j;
    float hr = hp[0], hz = hp[HID], hn = hp[2*HID];
    float hold = g_h[dir][s & 1][b*HID + j];

    float r = 1.f / (1.f + expf(-(xr + hr)));
    float z = 1.f / (1.f + expf(-(xz + hz)));
    float n = tanhf(xn + r * hn);
    float hnew = (1.f - z) * n + z * hold;

    g_h[dir][(s + 1) & 1][b*HID + j] = hnew;
    __nv_bfloat16 hi = __float2bfloat16(hnew);
    __nv_bfloat16 lo = __float2bfloat16(hnew - __bfloat162float(hi));
    g_hH[dir][b*KP + j] = hi;
    g_hL[dir][b*KP + j] = lo;
    if (valid)
        out[(size_t)(off + t) * (2*HID) + (size_t)dir*HID + j] = hnew;
}

// ---------------- launch ----------------
extern "C" void kernel_launch(void* const* d_in, const int* in_sizes, int n_in,
                              void* d_out, int out_size)
{
    const float* x     = (const float*)d_in[0];
    const int*   batch = (const int*)  d_in[1];
    int ib = 2;
    while (ib < n_in && in_sizes[ib] != HID) ib++;
    const float* bias  = (const float*)d_in[ib + 0];
    const float* wihf  = (const float*)d_in[ib + 1];
    const float* whhf  = (const float*)d_in[ib + 2];
    const float* bihf  = (const float*)d_in[ib + 3];
    const float* bhhf  = (const float*)d_in[ib + 4];
    const float* wihb  = (const float*)d_in[ib + 5];
    const float* whhb  = (const float*)d_in[ib + 6];
    const float* bihb  = (const float*)d_in[ib + 7];
    const float* bhhb  = (const float*)d_in[ib + 8];
    float* out = (float*)d_out;

    k_init <<<(BMOL + 255)/256, 256>>>();
    k_count<<<(NTOT + 255)/256, 256>>>(batch);
    k_scan <<<1, 1024>>>();
    k_h0   <<<BMOL, 320>>>(x);
    k_msgsplit<<<(NTOT*KP + 255)/256, 256>>>(x, bias);
    k_wsplit  <<<(4*WROWS*KP + 255)/256, 256>>>(wihf, wihb, whhf, whhb);

    // xp = msg @ Wih^T + b_ih, both dirs
    dim3 gx(NTOT/128, 8, 2);
    k_gemm_mma<<<gx, 256>>>(0, bihf, bihb);

    // recurrence
    dim3 gh(BMOL/128, 8, 2);
    for (int s = 0; s < MAXL; s++) {
        k_gemm_mma<<<gh, 256>>>(1, bhhf, bhhb);
        k_gates<<<(2*BMOL*HID + 255)/256, 256>>>(bihf, bihb, out, s);
    }
}